// round 2
// baseline (speedup 1.0000x reference)
#include <cuda_runtime.h>
#include <cstdint>

// Problem constants
#define BB   16384
#define AA   32
#define UU   64
#define SS   2048
#define EE   32
#define HYPD 64
#define HHD  4
#define NN   288      // H*HYP + E = 256 + 32
#define KKD  2048

#define NB3  (BB/8)   // attn kernel blocks (8 rows per block)

// ---------------- scratch (device globals; no allocation allowed) -------------
__device__ float g_Wcat[NN * KKD];   // packed+tf32-rounded weights [n][k]
__device__ float g_bias[NN];         // concatenated biases
__device__ float g_H1[BB * NN];      // relu(states@Wcat + bias)
__device__ float g_part[NB3 * 5];    // per-block partials: [mag, ent0..3]

__device__ __forceinline__ uint32_t f2tf(float f) {
    uint32_t u; asm("cvt.rna.tf32.f32 %0, %1;" : "=r"(u) : "f"(f)); return u;
}

__device__ __forceinline__ float warpsum(float v) {
    #pragma unroll
    for (int o = 16; o; o >>= 1) v += __shfl_xor_sync(0xffffffffu, v, o);
    return v;
}
__device__ __forceinline__ float warpmax(float v) {
    #pragma unroll
    for (int o = 16; o; o >>= 1) v = fmaxf(v, __shfl_xor_sync(0xffffffffu, v, o));
    return v;
}

// ---------------- kernel 0: pack Wcat (tf32-rounded) + bias -------------------
__global__ void pack_kernel(const float* __restrict__ sel_w1,
                            const float* __restrict__ sel_b1,
                            const float* __restrict__ v_w1,
                            const float* __restrict__ v_b1) {
    int idx = blockIdx.x * blockDim.x + threadIdx.x;
    if (idx < NN * KKD) {
        int n = idx / KKD;
        int k = idx - n * KKD;
        float v;
        if (n < 256) {
            int h = n >> 6, j = n & 63;                 // n = h*64 + j
            v = sel_w1[(h * SS + k) * HYPD + j];        // sel_w1[h][k][j]
        } else {
            v = v_w1[k * EE + (n - 256)];               // v_w1[k][e]
        }
        g_Wcat[idx] = __uint_as_float(f2tf(v));
    }
    if (idx < NN) {
        g_bias[idx] = (idx < 256) ? sel_b1[idx] : v_b1[idx - 256];
    }
}

// ---------------- kernel 1: GEMM [16384,2048]x[2048,288] tf32 mma.sync --------
#define BM 128
#define BKC 32
#define AST 36     // As row stride (conflict-free frag loads: 36 mod 32 = 4)
#define BST 36     // Bs row stride
// smem: As 2*128*36 + Bs 2*288*36 floats = 119808 bytes

__global__ __launch_bounds__(512, 1)
void gemm_kernel(const float* __restrict__ states) {
    extern __shared__ float sm[];
    float* As = sm;                        // [2][BM][AST]
    float* Bs = sm + 2 * BM * AST;         // [2][NN][BST]

    const int t    = threadIdx.x;
    const int lane = t & 31;
    const int warp = t >> 5;               // 0..15
    const int wM   = warp & 3;             // 4 warps along M
    const int wN   = warp >> 2;            // 4 warps along N
    const int grp  = lane >> 2;            // 0..7
    const int tid4 = lane & 3;             // 0..3
    const int rowBase = blockIdx.x * BM;

    // loader mapping: A — 1024 float4 per tile / 512 thr = 2 float4 each
    const int arow = t >> 2;               // 0..127
    const int ac4  = t & 3;                // float4 slot 0..3 (and +4)

    float acc[2][9][4];
    #pragma unroll
    for (int i = 0; i < 2; i++)
        #pragma unroll
        for (int j = 0; j < 9; j++)
            #pragma unroll
            for (int c = 0; c < 4; c++) acc[i][j][c] = 0.f;

    float4 ap0, ap1;
    float bpre[18];

    // ---- prefetch tile 0 ----
    {
        const float* ap = states + (size_t)(rowBase + arow) * KKD + ac4 * 4;
        ap0 = *(const float4*)ap;
        ap1 = *(const float4*)(ap + 16);
        #pragma unroll
        for (int i = 0; i < 18; i++) {
            int lin = i * 512 + t;
            int n = lin >> 5, kk = lin & 31;
            bpre[i] = g_Wcat[n * KKD + kk];
        }
    }
    // ---- store tile 0 into buffer 0 ----
    {
        float* a = As + arow * AST + ac4 * 4;
        a[0]  = __uint_as_float(f2tf(ap0.x));
        a[1]  = __uint_as_float(f2tf(ap0.y));
        a[2]  = __uint_as_float(f2tf(ap0.z));
        a[3]  = __uint_as_float(f2tf(ap0.w));
        a[16] = __uint_as_float(f2tf(ap1.x));
        a[17] = __uint_as_float(f2tf(ap1.y));
        a[18] = __uint_as_float(f2tf(ap1.z));
        a[19] = __uint_as_float(f2tf(ap1.w));
        #pragma unroll
        for (int i = 0; i < 18; i++) {
            int lin = i * 512 + t;
            int n = lin >> 5, kk = lin & 31;
            Bs[n * BST + kk] = bpre[i];    // already tf32-rounded
        }
    }
    __syncthreads();

    const int NITER = KKD / BKC;           // 64
    for (int it = 0; it < NITER; ++it) {
        const int cur = it & 1;
        if (it < NITER - 1) {
            const int k0 = (it + 1) * BKC;
            const float* ap = states + (size_t)(rowBase + arow) * KKD + k0 + ac4 * 4;
            ap0 = *(const float4*)ap;
            ap1 = *(const float4*)(ap + 16);
            #pragma unroll
            for (int i = 0; i < 18; i++) {
                int lin = i * 512 + t;
                int n = lin >> 5, kk = lin & 31;
                bpre[i] = g_Wcat[n * KKD + k0 + kk];
            }
        }
        // ---- compute from buffer cur ----
        const float* Ab = As + cur * BM * AST;
        const float* Bb = Bs + cur * NN * BST;
        #pragma unroll
        for (int kk = 0; kk < BKC; kk += 8) {
            uint32_t af[2][4];
            #pragma unroll
            for (int mt = 0; mt < 2; mt++) {
                int m0 = wM * 32 + mt * 16 + grp;
                af[mt][0] = __float_as_uint(Ab[m0 * AST + kk + tid4]);
                af[mt][1] = __float_as_uint(Ab[(m0 + 8) * AST + kk + tid4]);
                af[mt][2] = __float_as_uint(Ab[m0 * AST + kk + tid4 + 4]);
                af[mt][3] = __float_as_uint(Ab[(m0 + 8) * AST + kk + tid4 + 4]);
            }
            #pragma unroll
            for (int nt = 0; nt < 9; nt++) {
                int n0 = wN * 72 + nt * 8 + grp;
                uint32_t b0 = __float_as_uint(Bb[n0 * BST + kk + tid4]);
                uint32_t b1 = __float_as_uint(Bb[n0 * BST + kk + tid4 + 4]);
                #pragma unroll
                for (int mt = 0; mt < 2; mt++) {
                    asm volatile(
                        "mma.sync.aligned.m16n8k8.row.col.f32.tf32.tf32.f32 "
                        "{%0,%1,%2,%3}, {%4,%5,%6,%7}, {%8,%9}, {%0,%1,%2,%3};\n"
                        : "+f"(acc[mt][nt][0]), "+f"(acc[mt][nt][1]),
                          "+f"(acc[mt][nt][2]), "+f"(acc[mt][nt][3])
                        : "r"(af[mt][0]), "r"(af[mt][1]),
                          "r"(af[mt][2]), "r"(af[mt][3]),
                          "r"(b0), "r"(b1));
                }
            }
        }
        if (it < NITER - 1) {
            __syncthreads();
            const int nxt = cur ^ 1;
            float* a = As + nxt * BM * AST + arow * AST + ac4 * 4;
            a[0]  = __uint_as_float(f2tf(ap0.x));
            a[1]  = __uint_as_float(f2tf(ap0.y));
            a[2]  = __uint_as_float(f2tf(ap0.z));
            a[3]  = __uint_as_float(f2tf(ap0.w));
            a[16] = __uint_as_float(f2tf(ap1.x));
            a[17] = __uint_as_float(f2tf(ap1.y));
            a[18] = __uint_as_float(f2tf(ap1.z));
            a[19] = __uint_as_float(f2tf(ap1.w));
            float* bd = Bs + nxt * NN * BST;
            #pragma unroll
            for (int i = 0; i < 18; i++) {
                int lin = i * 512 + t;
                int n = lin >> 5, kk = lin & 31;
                bd[n * BST + kk] = bpre[i];
            }
            __syncthreads();
        }
    }

    // ---- epilogue: bias + relu -> g_H1 ----
    #pragma unroll
    for (int mt = 0; mt < 2; mt++) {
        int r0 = rowBase + wM * 32 + mt * 16 + grp;
        #pragma unroll
        for (int nt = 0; nt < 9; nt++) {
            int c0 = wN * 72 + nt * 8 + tid4 * 2;
            float b0 = g_bias[c0], b1 = g_bias[c0 + 1];
            g_H1[(size_t)r0 * NN + c0]           = fmaxf(acc[mt][nt][0] + b0, 0.f);
            g_H1[(size_t)r0 * NN + c0 + 1]       = fmaxf(acc[mt][nt][1] + b1, 0.f);
            g_H1[(size_t)(r0 + 8) * NN + c0]     = fmaxf(acc[mt][nt][2] + b0, 0.f);
            g_H1[(size_t)(r0 + 8) * NN + c0 + 1] = fmaxf(acc[mt][nt][3] + b1, 0.f);
        }
    }
}

// ---------------- kernel 2: selectors -> m -> logits -> softmax -> outputs ----
__global__ __launch_bounds__(256)
void attn_kernel(const float* __restrict__ states,
                 const float* __restrict__ sel_w2,
                 const float* __restrict__ key_w,
                 const float* __restrict__ v_w2,
                 const float* __restrict__ v_b2,
                 float* __restrict__ out) {
    __shared__ float hs[8][NN];
    __shared__ float sels[8][128];
    __shared__ float spart[8][5];

    const int t = threadIdx.x, lane = t & 31, w = t >> 5;
    const int b = blockIdx.x * 8 + w;

    // load h1 row (288 floats)
    #pragma unroll
    for (int i = 0; i < 9; i++) hs[w][i * 32 + lane] = g_H1[(size_t)b * NN + i * 32 + lane];
    __syncwarp();

    // selectors[h][e=lane] = sum_k h1[h*64+k] * sel_w2[h][k][e]
    #pragma unroll
    for (int h = 0; h < 4; h++) {
        float s = 0.f;
        #pragma unroll 8
        for (int k = 0; k < 64; k++)
            s += hs[w][h * 64 + k] * sel_w2[(h * 64 + k) * 32 + lane];
        sels[w][h * 32 + lane] = s;
    }
    __syncwarp();

    // v output: dot(relu_vhid, v_w2) + v_b2
    {
        float vp = hs[w][256 + lane] * v_w2[lane];
        vp = warpsum(vp);
        if (lane == 0) out[(size_t)BB * AA + b] = vp + v_b2[0];
    }

    // m[h][u] = sum_e key_w[h][u][e] * selectors[h][e]; lane holds u=lane, u=lane+32
    float m0[4], m1[4];
    #pragma unroll
    for (int h = 0; h < 4; h++) {
        float a0 = 0.f, a1 = 0.f;
        #pragma unroll 8
        for (int e = 0; e < 32; e++) {
            float se = sels[w][h * 32 + e];
            a0 += key_w[h * 2048 + lane * 32 + e] * se;
            a1 += key_w[h * 2048 + (lane + 32) * 32 + e] * se;
        }
        m0[h] = a0; m1[h] = a1;
    }

    // logits[h][a] = sum_u states[b][a*64+u] * m[h][u]
    float lg[4] = {0.f, 0.f, 0.f, 0.f};
    const float* srow = states + (size_t)b * SS;
    #pragma unroll 4
    for (int a = 0; a < 32; a++) {
        float v0 = srow[a * 64 + lane];
        float v1 = srow[a * 64 + 32 + lane];
        #pragma unroll
        for (int h = 0; h < 4; h++) {
            float p = v0 * m0[h] + v1 * m1[h];
            p = warpsum(p);
            if (lane == a) lg[h] = p;
        }
    }

    // softmax over agents (lane = a), stats
    const float invsq = 0.17677669529663687f;  // 1/sqrt(32)
    float ha = 0.f, mag = 0.f;
    float entp[4];
    #pragma unroll
    for (int h = 0; h < 4; h++) {
        mag += lg[h] * lg[h];
        float z = lg[h] * invsq;
        float mx = warpmax(z);
        float e = __expf(z - mx);
        float ssum = warpsum(e);
        float wgt = e / ssum;
        ha += wgt;
        entp[h] = warpsum(wgt * __logf(wgt + 1e-8f));
    }
    mag = warpsum(mag);

    out[(size_t)b * AA + lane] = ha;  // head_attend

    if (lane == 0) {
        spart[w][0] = mag;
        #pragma unroll
        for (int h = 0; h < 4; h++) spart[w][1 + h] = entp[h];
    }
    __syncthreads();
    if (t == 0) {
        float acc[5] = {0, 0, 0, 0, 0};
        for (int ww = 0; ww < 8; ww++)
            #pragma unroll
            for (int c = 0; c < 5; c++) acc[c] += spart[ww][c];
        #pragma unroll
        for (int c = 0; c < 5; c++) g_part[blockIdx.x * 5 + c] = acc[c];
    }
}

// ---------------- kernel 3: deterministic finalize ----------------------------
__global__ void finalize_kernel(float* __restrict__ out) {
    __shared__ float red[256];
    const int t = threadIdx.x;
    for (int c = 0; c < 5; c++) {
        float s = 0.f;
        for (int j = t; j < NB3; j += 256) s += g_part[j * 5 + c];
        red[t] = s;
        __syncthreads();
        #pragma unroll
        for (int o = 128; o; o >>= 1) {
            if (t < o) red[t] += red[t + o];
            __syncthreads();
        }
        if (t == 0) {
            if (c == 0)
                out[(size_t)BB * AA + BB] = 1e-3f * red[0] / (float)((size_t)BB * AA);
            else
                out[(size_t)BB * AA + BB + c] = -red[0] / (float)BB;
        }
        __syncthreads();
    }
}

// ---------------- launch ------------------------------------------------------
extern "C" void kernel_launch(void* const* d_in, const int* in_sizes, int n_in,
                              void* d_out, int out_size) {
    (void)in_sizes; (void)n_in; (void)out_size;
    // metadata order: agent_qs, states, sel_w1, sel_b1, sel_w2, key_w, v_w1, v_b1, v_w2, v_b2
    const float* states = (const float*)d_in[1];
    const float* sel_w1 = (const float*)d_in[2];
    const float* sel_b1 = (const float*)d_in[3];
    const float* sel_w2 = (const float*)d_in[4];
    const float* key_w  = (const float*)d_in[5];
    const float* v_w1   = (const float*)d_in[6];
    const float* v_b1   = (const float*)d_in[7];
    const float* v_w2   = (const float*)d_in[8];
    const float* v_b2   = (const float*)d_in[9];
    float* out = (float*)d_out;

    const int smem = (int)(2 * (BM * AST + NN * BST) * sizeof(float));  // 119808
    cudaFuncSetAttribute(gemm_kernel, cudaFuncAttributeMaxDynamicSharedMemorySize, smem);

    pack_kernel<<<(NN * KKD + 1023) / 1024, 1024>>>(sel_w1, sel_b1, v_w1, v_b1);
    gemm_kernel<<<BB / BM, 512, smem>>>(states);
    attn_kernel<<<NB3, 256>>>(states, sel_w2, key_w, v_w2, v_b2, out);
    finalize_kernel<<<1, 256>>>(out);
}

// round 4
// speedup vs baseline: 4.1920x; 4.1920x over previous
#include <cuda_runtime.h>
#include <cstdint>

// Problem constants
#define BB   16384
#define AA   32
#define UU   64
#define SS   2048
#define EE   32
#define HYPD 64
#define HHD  4
#define NN   288      // H*HYP + E = 256 + 32
#define KKD  2048

#define NB3  (BB/8)   // attn kernel blocks (8 rows per block)

// ---------------- scratch (device globals; no allocation allowed) -------------
__device__ float g_Wcat[NN * KKD];   // packed+tf32-rounded weights [n][k]
__device__ float g_bias[NN];         // concatenated biases
__device__ float g_H1[BB * NN];      // relu(states@Wcat + bias)
__device__ float g_keyT[HHD * EE * UU]; // key_w transposed to [h][e][u]
__device__ float g_part[NB3 * 5];    // per-block partials: [mag, ent0..3]

__device__ __forceinline__ uint32_t f2tf(float f) {
    uint32_t u; asm("cvt.rna.tf32.f32 %0, %1;" : "=r"(u) : "f"(f)); return u;
}

__device__ __forceinline__ float warpsum(float v) {
    #pragma unroll
    for (int o = 16; o; o >>= 1) v += __shfl_xor_sync(0xffffffffu, v, o);
    return v;
}
__device__ __forceinline__ float warpmax(float v) {
    #pragma unroll
    for (int o = 16; o; o >>= 1) v = fmaxf(v, __shfl_xor_sync(0xffffffffu, v, o));
    return v;
}

// ---------------- kernel 0: pack Wcat (tf32-rounded) + bias + key transpose ---
__global__ void pack_kernel(const float* __restrict__ sel_w1,
                            const float* __restrict__ sel_b1,
                            const float* __restrict__ v_w1,
                            const float* __restrict__ v_b1,
                            const float* __restrict__ key_w) {
    int idx = blockIdx.x * blockDim.x + threadIdx.x;
    if (idx < NN * KKD) {
        int n = idx / KKD;
        int k = idx - n * KKD;
        float v;
        if (n < 256) {
            int h = n >> 6, j = n & 63;                 // n = h*64 + j
            v = sel_w1[(h * SS + k) * HYPD + j];        // sel_w1[h][k][j]
        } else {
            v = v_w1[k * EE + (n - 256)];               // v_w1[k][e]
        }
        g_Wcat[idx] = __uint_as_float(f2tf(v));
    }
    if (idx < NN) {
        g_bias[idx] = (idx < 256) ? sel_b1[idx] : v_b1[idx - 256];
    }
    if (idx < HHD * UU * EE) {
        // key_w layout [h][u][e]  ->  g_keyT [h][e][u]
        int h = idx >> 11;
        int r = idx & 2047;
        int u = r >> 5;
        int e = r & 31;
        g_keyT[h * 2048 + e * 64 + u] = key_w[idx];
    }
}

// ---------------- kernel 1: GEMM [16384,2048]x[2048,288] tf32 mma.sync --------
#define BM 128
#define BKC 32
#define AST 36     // As row stride (conflict-free frag loads)
#define BST 36     // Bs row stride
// smem: As 2*128*36 + Bs 2*288*36 floats = 119808 bytes

__global__ __launch_bounds__(512, 1)
void gemm_kernel(const float* __restrict__ states) {
    extern __shared__ float sm[];
    float* As = sm;                        // [2][BM][AST]
    float* Bs = sm + 2 * BM * AST;         // [2][NN][BST]

    const int t    = threadIdx.x;
    const int lane = t & 31;
    const int warp = t >> 5;               // 0..15
    const int wM   = warp & 3;             // 4 warps along M
    const int wN   = warp >> 2;            // 4 warps along N
    const int grp  = lane >> 2;            // 0..7
    const int tid4 = lane & 3;             // 0..3
    const int rowBase = blockIdx.x * BM;

    const int arow = t >> 2;               // 0..127
    const int ac4  = t & 3;                // float4 slot

    float acc[2][9][4];
    #pragma unroll
    for (int i = 0; i < 2; i++)
        #pragma unroll
        for (int j = 0; j < 9; j++)
            #pragma unroll
            for (int c = 0; c < 4; c++) acc[i][j][c] = 0.f;

    float4 ap0, ap1;
    float bpre[18];

    // ---- prefetch tile 0 ----
    {
        const float* ap = states + (size_t)(rowBase + arow) * KKD + ac4 * 4;
        ap0 = *(const float4*)ap;
        ap1 = *(const float4*)(ap + 16);
        #pragma unroll
        for (int i = 0; i < 18; i++) {
            int lin = i * 512 + t;
            int n = lin >> 5, kk = lin & 31;
            bpre[i] = g_Wcat[n * KKD + kk];
        }
    }
    // ---- store tile 0 into buffer 0 ----
    {
        float* a = As + arow * AST + ac4 * 4;
        a[0]  = __uint_as_float(f2tf(ap0.x));
        a[1]  = __uint_as_float(f2tf(ap0.y));
        a[2]  = __uint_as_float(f2tf(ap0.z));
        a[3]  = __uint_as_float(f2tf(ap0.w));
        a[16] = __uint_as_float(f2tf(ap1.x));
        a[17] = __uint_as_float(f2tf(ap1.y));
        a[18] = __uint_as_float(f2tf(ap1.z));
        a[19] = __uint_as_float(f2tf(ap1.w));
        #pragma unroll
        for (int i = 0; i < 18; i++) {
            int lin = i * 512 + t;
            int n = lin >> 5, kk = lin & 31;
            Bs[n * BST + kk] = bpre[i];
        }
    }
    __syncthreads();

    const int NITER = KKD / BKC;           // 64
    for (int it = 0; it < NITER; ++it) {
        const int cur = it & 1;
        if (it < NITER - 1) {
            const int k0 = (it + 1) * BKC;
            const float* ap = states + (size_t)(rowBase + arow) * KKD + k0 + ac4 * 4;
            ap0 = *(const float4*)ap;
            ap1 = *(const float4*)(ap + 16);
            #pragma unroll
            for (int i = 0; i < 18; i++) {
                int lin = i * 512 + t;
                int n = lin >> 5, kk = lin & 31;
                bpre[i] = g_Wcat[n * KKD + k0 + kk];
            }
        }
        // ---- compute from buffer cur ----
        const float* Ab = As + cur * BM * AST;
        const float* Bb = Bs + cur * NN * BST;
        #pragma unroll
        for (int kk = 0; kk < BKC; kk += 8) {
            uint32_t af[2][4];
            #pragma unroll
            for (int mt = 0; mt < 2; mt++) {
                int m0 = wM * 32 + mt * 16 + grp;
                af[mt][0] = __float_as_uint(Ab[m0 * AST + kk + tid4]);
                af[mt][1] = __float_as_uint(Ab[(m0 + 8) * AST + kk + tid4]);
                af[mt][2] = __float_as_uint(Ab[m0 * AST + kk + tid4 + 4]);
                af[mt][3] = __float_as_uint(Ab[(m0 + 8) * AST + kk + tid4 + 4]);
            }
            #pragma unroll
            for (int nt = 0; nt < 9; nt++) {
                int n0 = wN * 72 + nt * 8 + grp;
                uint32_t b0 = __float_as_uint(Bb[n0 * BST + kk + tid4]);
                uint32_t b1 = __float_as_uint(Bb[n0 * BST + kk + tid4 + 4]);
                #pragma unroll
                for (int mt = 0; mt < 2; mt++) {
                    asm volatile(
                        "mma.sync.aligned.m16n8k8.row.col.f32.tf32.tf32.f32 "
                        "{%0,%1,%2,%3}, {%4,%5,%6,%7}, {%8,%9}, {%0,%1,%2,%3};\n"
                        : "+f"(acc[mt][nt][0]), "+f"(acc[mt][nt][1]),
                          "+f"(acc[mt][nt][2]), "+f"(acc[mt][nt][3])
                        : "r"(af[mt][0]), "r"(af[mt][1]),
                          "r"(af[mt][2]), "r"(af[mt][3]),
                          "r"(b0), "r"(b1));
                }
            }
        }
        if (it < NITER - 1) {
            __syncthreads();
            const int nxt = cur ^ 1;
            float* a = As + nxt * BM * AST + arow * AST + ac4 * 4;
            a[0]  = __uint_as_float(f2tf(ap0.x));
            a[1]  = __uint_as_float(f2tf(ap0.y));
            a[2]  = __uint_as_float(f2tf(ap0.z));
            a[3]  = __uint_as_float(f2tf(ap0.w));
            a[16] = __uint_as_float(f2tf(ap1.x));
            a[17] = __uint_as_float(f2tf(ap1.y));
            a[18] = __uint_as_float(f2tf(ap1.z));
            a[19] = __uint_as_float(f2tf(ap1.w));
            float* bd = Bs + nxt * NN * BST;
            #pragma unroll
            for (int i = 0; i < 18; i++) {
                int lin = i * 512 + t;
                int n = lin >> 5, kk = lin & 31;
                bd[n * BST + kk] = bpre[i];
            }
            __syncthreads();
        }
    }

    // ---- epilogue: bias + relu -> g_H1 ----
    #pragma unroll
    for (int mt = 0; mt < 2; mt++) {
        int r0 = rowBase + wM * 32 + mt * 16 + grp;
        #pragma unroll
        for (int nt = 0; nt < 9; nt++) {
            int c0 = wN * 72 + nt * 8 + tid4 * 2;
            float b0 = g_bias[c0], b1 = g_bias[c0 + 1];
            g_H1[(size_t)r0 * NN + c0]           = fmaxf(acc[mt][nt][0] + b0, 0.f);
            g_H1[(size_t)r0 * NN + c0 + 1]       = fmaxf(acc[mt][nt][1] + b1, 0.f);
            g_H1[(size_t)(r0 + 8) * NN + c0]     = fmaxf(acc[mt][nt][2] + b0, 0.f);
            g_H1[(size_t)(r0 + 8) * NN + c0 + 1] = fmaxf(acc[mt][nt][3] + b1, 0.f);
        }
    }
}

// ---------------- kernel 2: selectors -> m -> logits -> softmax -> outputs ----
// One warp per batch row. All global loads coalesced. Logits reduction via
// butterfly transpose-reduce (31 shfl rounds for all 32 agents), after which
// lane == agent, so softmax/entropy/head_attend are direct lane-wise ops.
__global__ __launch_bounds__(256)
void attn_kernel(const float* __restrict__ states,
                 const float* __restrict__ sel_w2,
                 const float* __restrict__ v_w2,
                 const float* __restrict__ v_b2,
                 float* __restrict__ out) {
    __shared__ float hs[8][NN];
    __shared__ float sels[8][128];
    __shared__ float spart[8][5];

    const int t = threadIdx.x, lane = t & 31, w = t >> 5;
    const int b = blockIdx.x * 8 + w;

    // load h1 row (288 floats, coalesced)
    #pragma unroll
    for (int i = 0; i < 9; i++) hs[w][i * 32 + lane] = g_H1[(size_t)b * NN + i * 32 + lane];
    __syncwarp();

    // selectors[h][e=lane] = sum_k h1[h*64+k] * sel_w2[h][k][e]   (coalesced in e)
    #pragma unroll
    for (int h = 0; h < 4; h++) {
        float s = 0.f;
        const float* w2h = sel_w2 + h * 64 * 32 + lane;
        #pragma unroll 8
        for (int k = 0; k < 64; k++)
            s += hs[w][h * 64 + k] * w2h[k * 32];
        sels[w][h * 32 + lane] = s;
    }
    __syncwarp();

    // v output: dot(relu_vhid, v_w2) + v_b2
    {
        float vp = hs[w][256 + lane] * v_w2[lane];
        vp = warpsum(vp);
        if (lane == 0) out[(size_t)BB * AA + b] = vp + v_b2[0];
    }

    // m[h][u] from transposed key weights (coalesced in u): lane holds u=lane, lane+32
    float m0[4], m1[4];
    #pragma unroll
    for (int h = 0; h < 4; h++) {
        float a0 = 0.f, a1 = 0.f;
        const float* kh = g_keyT + h * 2048 + lane;
        #pragma unroll 8
        for (int e = 0; e < 32; e++) {
            float se = sels[w][h * 32 + e];
            a0 += kh[e * 64] * se;
            a1 += kh[e * 64 + 32] * se;
        }
        m0[h] = a0; m1[h] = a1;
    }

    // Load full state row (coalesced): v0[a] = s[b][a*64+lane], v1[a] = s[b][a*64+32+lane]
    const float* srow = states + (size_t)b * SS;
    float v0[32], v1[32];
    #pragma unroll
    for (int a = 0; a < 32; a++) {
        v0[a] = srow[a * 64 + lane];
        v1[a] = srow[a * 64 + 32 + lane];
    }

    // logits[h][a] = sum_u s[b][a*64+u] * m[h][u], via butterfly transpose-reduce.
    // After reduction, lane a holds logits[h][a].
    float lg[4];
    #pragma unroll
    for (int h = 0; h < 4; h++) {
        float vals[32];
        #pragma unroll
        for (int a = 0; a < 32; a++)
            vals[a] = v0[a] * m0[h] + v1[a] * m1[h];
        #pragma unroll
        for (int m = 16; m >= 1; m >>= 1) {
            #pragma unroll
            for (int jj = 0; jj < m; jj++) {
                float lo = vals[jj], hi = vals[jj + m];
                float send = (lane & m) ? lo : hi;
                float recv = __shfl_xor_sync(0xffffffffu, send, m);
                vals[jj] = ((lane & m) ? hi : lo) + recv;
            }
        }
        lg[h] = vals[0];
    }

    // softmax over agents (lane = a), stats
    const float invsq = 0.17677669529663687f;  // 1/sqrt(32)
    float ha = 0.f, mag = 0.f;
    float entp[4];
    #pragma unroll
    for (int h = 0; h < 4; h++) {
        mag += lg[h] * lg[h];
        float z = lg[h] * invsq;
        float mx = warpmax(z);
        float e = __expf(z - mx);
        float ssum = warpsum(e);
        float wgt = e / ssum;
        ha += wgt;
        entp[h] = warpsum(wgt * __logf(wgt + 1e-8f));
    }
    mag = warpsum(mag);

    out[(size_t)b * AA + lane] = ha;  // head_attend

    if (lane == 0) {
        spart[w][0] = mag;
        #pragma unroll
        for (int h = 0; h < 4; h++) spart[w][1 + h] = entp[h];
    }
    __syncthreads();
    if (t == 0) {
        float acc[5] = {0, 0, 0, 0, 0};
        for (int ww = 0; ww < 8; ww++)
            #pragma unroll
            for (int c = 0; c < 5; c++) acc[c] += spart[ww][c];
        #pragma unroll
        for (int c = 0; c < 5; c++) g_part[blockIdx.x * 5 + c] = acc[c];
    }
}

// ---------------- kernel 3: deterministic finalize (single pass) --------------
__global__ __launch_bounds__(256)
void finalize_kernel(float* __restrict__ out) {
    __shared__ float red[8][5];
    const int t = threadIdx.x, lane = t & 31, w = t >> 5;
    float acc[5] = {0, 0, 0, 0, 0};
    for (int j = t; j < NB3; j += 256) {
        #pragma unroll
        for (int c = 0; c < 5; c++) acc[c] += g_part[j * 5 + c];
    }
    #pragma unroll
    for (int c = 0; c < 5; c++) acc[c] = warpsum(acc[c]);
    if (lane == 0)
        #pragma unroll
        for (int c = 0; c < 5; c++) red[w][c] = acc[c];
    __syncthreads();
    if (t == 0) {
        float fin[5] = {0, 0, 0, 0, 0};
        #pragma unroll
        for (int ww = 0; ww < 8; ww++)
            #pragma unroll
            for (int c = 0; c < 5; c++) fin[c] += red[ww][c];
        out[(size_t)BB * AA + BB] = 1e-3f * fin[0] / (float)((size_t)BB * AA);
        #pragma unroll
        for (int c = 1; c < 5; c++)
            out[(size_t)BB * AA + BB + c] = -fin[c] / (float)BB;
    }
}

// ---------------- launch ------------------------------------------------------
extern "C" void kernel_launch(void* const* d_in, const int* in_sizes, int n_in,
                              void* d_out, int out_size) {
    (void)in_sizes; (void)n_in; (void)out_size;
    // metadata order: agent_qs, states, sel_w1, sel_b1, sel_w2, key_w, v_w1, v_b1, v_w2, v_b2
    const float* states = (const float*)d_in[1];
    const float* sel_w1 = (const float*)d_in[2];
    const float* sel_b1 = (const float*)d_in[3];
    const float* sel_w2 = (const float*)d_in[4];
    const float* key_w  = (const float*)d_in[5];
    const float* v_w1   = (const float*)d_in[6];
    const float* v_b1   = (const float*)d_in[7];
    const float* v_w2   = (const float*)d_in[8];
    const float* v_b2   = (const float*)d_in[9];
    float* out = (float*)d_out;

    const int smem = (int)(2 * (BM * AST + NN * BST) * sizeof(float));  // 119808
    cudaFuncSetAttribute(gemm_kernel, cudaFuncAttributeMaxDynamicSharedMemorySize, smem);

    pack_kernel<<<(NN * KKD + 1023) / 1024, 1024>>>(sel_w1, sel_b1, v_w1, v_b1, key_w);
    gemm_kernel<<<BB / BM, 512, smem>>>(states);
    attn_kernel<<<NB3, 256>>>(states, sel_w2, v_w2, v_b2, out);
    finalize_kernel<<<1, 256>>>(out);
}